// round 12
// baseline (speedup 1.0000x reference)
#include <cuda_runtime.h>
#include <cuda_fp16.h>
#include <math_constants.h>
#include <cstdint>

#define BATCH 4
#define SEQ   2048
#define DM    1024

#define BM 128
#define BN 256
#define BK 32                       // fp16 per chunk (64 bytes per row)
#define NTHREADS 512
#define STAGES 4
#define A_BYTES (128 * 64)          // 128x32 fp16 = 8192 B
#define B_BYTES (256 * 64)          // 256x32 fp16 = 16384 B
#define STAGE_BYTES (A_BYTES + B_BYTES)    // 24576 B
#define SMEM_TOTAL (STAGES * STAGE_BYTES)  // 98304 B

// ---------------------------------------------------------------------------
// Scratch (allocation-free)
// ---------------------------------------------------------------------------
__device__ __half g_x16[(size_t)BATCH*SEQ*DM];
__device__ __half g_W16[(size_t)3*DM*DM];
__device__ __half g_QKV16[(size_t)3*BATCH*SEQ*DM];
__device__ __half g_Vt16[(size_t)BATCH*DM*SEQ];
__device__ __half g_P16[(size_t)BATCH*SEQ*SEQ];

// ---------------------------------------------------------------------------
// PTX helpers (base sm_80+ features only)
// ---------------------------------------------------------------------------
__device__ __forceinline__ uint32_t smem_u32(const void* p) {
    uint32_t a;
    asm("{ .reg .u64 t; cvta.to.shared.u64 t, %1; cvt.u32.u64 %0, t; }" : "=r"(a) : "l"(p));
    return a;
}
__device__ __forceinline__ void cp_async16(uint32_t s, const void* g) {
    asm volatile("cp.async.cg.shared.global [%0], [%1], 16;" :: "r"(s), "l"(g));
}
#define CP_COMMIT() asm volatile("cp.async.commit_group;" ::: "memory")
#define CP_WAIT2()  asm volatile("cp.async.wait_group 2;" ::: "memory")

__device__ __forceinline__ void ldmx4(uint32_t* r, uint32_t a) {
    asm volatile("ldmatrix.sync.aligned.m8n8.x4.shared.b16 {%0,%1,%2,%3}, [%4];"
        : "=r"(r[0]), "=r"(r[1]), "=r"(r[2]), "=r"(r[3]) : "r"(a));
}
__device__ __forceinline__ void mma16816(float* c, const uint32_t* a, const uint32_t* b) {
    asm volatile("mma.sync.aligned.m16n8k16.row.col.f32.f16.f16.f32 "
        "{%0,%1,%2,%3}, {%4,%5,%6,%7}, {%8,%9}, {%0,%1,%2,%3};"
        : "+f"(c[0]), "+f"(c[1]), "+f"(c[2]), "+f"(c[3])
        : "r"(a[0]), "r"(a[1]), "r"(a[2]), "r"(a[3]), "r"(b[0]), "r"(b[1]));
}

// Swizzled smem byte offset for (row, 16B-chunk c16) inside an Nx32-fp16 tile.
__device__ __forceinline__ uint32_t sw_off(int row, int c16) {
    return (uint32_t)(row * 64 + ((c16 ^ ((row >> 1) & 3)) << 4));
}

// ---------------------------------------------------------------------------
// fp16 NT GEMM via mma.sync: C[128,256] = A[M,K] @ B[N,K]^T, fp32 accumulate.
// 512 threads = 16 warps (4 along M x 4 along N), warp tile 32x64.
// 4 warps/SMSP for issue-density; 1 CTA/SM (full register file).
// revM: reverse m-tile order (LPT schedule for causal-K truncated GEMM).
// ---------------------------------------------------------------------------
__global__ __launch_bounds__(NTHREADS, 1) void gemm_f16(
    const __half* __restrict__ A, const __half* __restrict__ B,
    float* __restrict__ outF, __half* __restrict__ outH,
    int lda, int ldb, int ldc, long sA, long sB, long sC,
    float alpha, int Ktot, int causalSkip, int causalK, int revM)
{
    const int mTile = revM ? (int)(gridDim.y - 1 - blockIdx.y) : (int)blockIdx.y;
    const int m0 = mTile * BM;
    const int n0 = blockIdx.x * BN;
    if (causalSkip && n0 >= m0 + BM) return;

    extern __shared__ char smem[];
    const uint32_t sb = smem_u32(smem);

    const int tid  = threadIdx.x;
    const int lane = tid & 31;
    const int wid  = tid >> 5;
    const int warpM0 = (wid >> 2) * 32;   // 4 warps along M, 32 rows each
    const int warpN0 = (wid & 3) * 64;    // 4 warps along N, 64 cols each

    A += (size_t)blockIdx.z * sA;
    B += (size_t)blockIdx.z * sB;

    const int kEnd = causalK ? min(Ktot, m0 + BM) : Ktot;
    const int nCh = kEnd / BK;

    auto issue = [&](int c) {
        const uint32_t st = sb + (uint32_t)(c & (STAGES - 1)) * STAGE_BYTES;
        const int k0 = c * BK;
        // A: 512 16B chunks (1 per thread)
        {
            const int row = tid >> 2, c16 = tid & 3;
            cp_async16(st + sw_off(row, c16),
                       A + (size_t)(m0 + row) * lda + k0 + c16 * 8);
        }
        // B: 1024 16B chunks (2 per thread)
#pragma unroll
        for (int r = 0; r < 2; r++) {
            const int i = tid + r * NTHREADS;
            const int row = i >> 2, c16 = i & 3;
            cp_async16(st + A_BYTES + sw_off(row, c16),
                       B + (size_t)(n0 + row) * ldb + k0 + c16 * 8);
        }
    };

    float acc[2][8][4];
#pragma unroll
    for (int i = 0; i < 2; i++)
#pragma unroll
        for (int j = 0; j < 8; j++)
#pragma unroll
            for (int k = 0; k < 4; k++) acc[i][j][k] = 0.f;

    // prologue: 3 stages in flight
#pragma unroll
    for (int s = 0; s < STAGES - 1; s++) {
        if (s < nCh) issue(s);
        CP_COMMIT();
    }

    const int aRow = (lane & 15);
    const int aHi  = (lane >> 4);
    const int bRow = (lane & 7) + ((lane >> 4) << 3);   // B pair: n8 tile / tile+1
    const int bHi  = ((lane >> 3) & 1);

    for (int c = 0; c < nCh; c++) {
        CP_WAIT2();
        __syncthreads();
        if (c + STAGES - 1 < nCh) issue(c + STAGES - 1);
        CP_COMMIT();

        const uint32_t st = sb + (uint32_t)(c & (STAGES - 1)) * STAGE_BYTES;
#pragma unroll
        for (int ks = 0; ks < 2; ks++) {
            uint32_t af[2][4], bf[4][4];
#pragma unroll
            for (int mf = 0; mf < 2; mf++)
                ldmx4(af[mf], st + sw_off(warpM0 + mf * 16 + aRow, ks * 2 + aHi));
#pragma unroll
            for (int nfp = 0; nfp < 4; nfp++)
                ldmx4(bf[nfp], st + A_BYTES +
                      sw_off(warpN0 + nfp * 16 + bRow, ks * 2 + bHi));
#pragma unroll
            for (int nfp = 0; nfp < 4; nfp++)
#pragma unroll
                for (int mf = 0; mf < 2; mf++) {
                    mma16816(acc[mf][2*nfp],     af[mf], bf[nfp] + 0);
                    mma16816(acc[mf][2*nfp + 1], af[mf], bf[nfp] + 2);
                }
        }
    }

    // epilogue
    const long cb = (long)blockIdx.z * sC;
    const int rBase = m0 + warpM0 + (lane >> 2);
    const int cBase = n0 + warpN0 + (lane & 3) * 2;
#pragma unroll
    for (int mf = 0; mf < 2; mf++) {
#pragma unroll
        for (int nf = 0; nf < 8; nf++) {
            const int col = cBase + nf * 8;
#pragma unroll
            for (int h = 0; h < 2; h++) {
                const int row = rBase + mf * 16 + h * 8;
                const float v0 = acc[mf][nf][2 * h] * alpha;
                const float v1 = acc[mf][nf][2 * h + 1] * alpha;
                if (outF) {
                    *(float2*)(outF + cb + (size_t)row * ldc + col) =
                        make_float2(v0, v1);
                } else {
                    *(__half2*)(outH + cb + (size_t)row * ldc + col) =
                        __floats2half2_rn(v0, v1);
                }
            }
        }
    }
}

// ---------------------------------------------------------------------------
// One fused fp32->fp16 convert for x, Wq, Wk, Wv.
// ---------------------------------------------------------------------------
#define XN4 (BATCH*SEQ*DM/4)
#define WN4 (DM*DM/4)
__global__ __launch_bounds__(256) void to_f16_all(
    const float* __restrict__ x, const float* __restrict__ Wq,
    const float* __restrict__ Wk, const float* __restrict__ Wv,
    __half* __restrict__ x16, __half* __restrict__ W16)
{
    int i = blockIdx.x * 256 + threadIdx.x;
    const float* src;
    __half* dst;
    int off;
    if (i < XN4) { src = x; dst = x16; off = i; }
    else {
        int j = i - XN4;
        int w = j / WN4;
        off = j - w * WN4;
        src = (w == 0) ? Wq : (w == 1) ? Wk : Wv;
        dst = W16 + (size_t)w * DM * DM;
        if (i >= XN4 + 3 * WN4) return;
    }
    float4 v = ((const float4*)src)[off];
    __half2* D = (__half2*)dst + 2 * (size_t)off;
    D[0] = __floats2half2_rn(v.x, v.y);
    D[1] = __floats2half2_rn(v.z, v.w);
}

// src [B][SEQ][DM] -> dst [B][DM][SEQ]
__global__ __launch_bounds__(256) void transpose_f16(
    const __half* __restrict__ src, __half* __restrict__ dst)
{
    __shared__ __half t[64][65];
    const int b  = blockIdx.z;
    const int n0 = blockIdx.x * 64;
    const int k0 = blockIdx.y * 64;
    const int tx = threadIdx.x & 31, ty = threadIdx.x >> 5;

    const __half* s = src + ((size_t)b * SEQ + k0) * DM + n0;
#pragma unroll
    for (int i = 0; i < 8; i++) {
        int r = ty + i * 8;
        __half2 v = *(const __half2*)(s + (size_t)r * DM + 2 * tx);
        t[r][2*tx] = __low2half(v); t[r][2*tx+1] = __high2half(v);
    }
    __syncthreads();
    __half* d = dst + ((size_t)b * DM + n0) * SEQ + k0;
#pragma unroll
    for (int i = 0; i < 8; i++) {
        int rn = ty + i * 8;
        *(__half2*)(d + (size_t)rn * SEQ + 2 * tx) =
            __halves2half2(t[2*tx][rn], t[2*tx+1][rn]);
    }
}

// Causal softmax, in place on fp16 P. Reads k <= q only; zero-fills (q, 128-boundary).
__global__ __launch_bounds__(256) void softmax_causal(__half* __restrict__ P16)
{
    const int q = blockIdx.x, b = blockIdx.y;
    __half* row = P16 + ((size_t)b * SEQ + q) * SEQ;
    const int len = q + 1, tid = threadIdx.x;

    __shared__ float sred[8];
    __shared__ float sbc;

    float vals[8]; int n = 0;
    float m = -CUDART_INF_F;
    for (int i = tid; i < len; i += 256) {
        float v = __half2float(row[i]);
        vals[n++] = v;
        m = fmaxf(m, v);
    }
#pragma unroll
    for (int o = 16; o; o >>= 1) m = fmaxf(m, __shfl_xor_sync(0xffffffffu, m, o));
    if ((tid & 31) == 0) sred[tid >> 5] = m;
    __syncthreads();
    if (tid == 0) {
        float t = sred[0];
#pragma unroll
        for (int w = 1; w < 8; w++) t = fmaxf(t, sred[w]);
        sbc = t;
    }
    __syncthreads();
    m = sbc;

    float s = 0.f;
#pragma unroll
    for (int k = 0; k < 8; k++)
        if (k < n) { float e = expf(vals[k] - m); vals[k] = e; s += e; }
#pragma unroll
    for (int o = 16; o; o >>= 1) s += __shfl_xor_sync(0xffffffffu, s, o);
    __syncthreads();
    if ((tid & 31) == 0) sred[tid >> 5] = s;
    __syncthreads();
    if (tid == 0) {
        float t = 0.f;
#pragma unroll
        for (int w = 0; w < 8; w++) t += sred[w];
        sbc = 1.f / t;
    }
    __syncthreads();
    const float inv = sbc;

    n = 0;
    for (int i = tid; i < len; i += 256) row[i] = __float2half_rn(vals[n++] * inv);

    const __half z = __float2half_rn(0.f);
    const int tileEnd = ((q >> 7) + 1) << 7;
    for (int i = len + tid; i < tileEnd; i += 256) row[i] = z;
}

// ---------------------------------------------------------------------------
extern "C" void kernel_launch(void* const* d_in, const int* in_sizes, int n_in,
                              void* d_out, int out_size)
{
    const float* x  = (const float*)d_in[0];
    const float* Wq = (const float*)d_in[1];
    const float* Wk = (const float*)d_in[2];
    const float* Wv = (const float*)d_in[3];
    float* out = (float*)d_out;

    __half *x16, *W16, *QKV16, *Vt16, *P16;
    cudaGetSymbolAddress((void**)&x16, g_x16);
    cudaGetSymbolAddress((void**)&W16, g_W16);
    cudaGetSymbolAddress((void**)&QKV16, g_QKV16);
    cudaGetSymbolAddress((void**)&Vt16, g_Vt16);
    cudaGetSymbolAddress((void**)&P16, g_P16);

    const long BSD = (long)BATCH * SEQ * DM;
    const long SD  = (long)SEQ * DM;
    const long SS  = (long)SEQ * SEQ;

    cudaFuncSetAttribute(gemm_f16, cudaFuncAttributeMaxDynamicSharedMemorySize, SMEM_TOTAL);

    // 1) fused fp32 -> fp16 conversion (x + Wq + Wk + Wv)
    {
        const int total = XN4 + 3 * WN4;
        to_f16_all<<<(total + 255) / 256, 256>>>(x, Wq, Wk, Wv, x16, W16);
    }

    // 2) Fused QKV projection (z selects weight + output section; A fixed)
    {
        dim3 g(DM / BN, (BATCH * SEQ) / BM, 3);
        gemm_f16<<<g, NTHREADS, SMEM_TOTAL>>>(x16, W16,
            nullptr, QKV16,
            DM, DM, DM, 0, (long)DM * DM, BSD,
            1.f, DM, 0, 0, 0);
    }

    // 3) V transpose: [B][S][DM] -> [B][DM][S]
    {
        dim3 g(DM / 64, SEQ / 64, BATCH);
        transpose_f16<<<g, 256>>>(QKV16 + 2 * BSD, Vt16);
    }

    // 4) Scores -> fp16 P directly: P = (1/32) Q @ K^T (causal tile skip)
    {
        dim3 g(SEQ / BN, SEQ / BM, BATCH);
        gemm_f16<<<g, NTHREADS, SMEM_TOTAL>>>(QKV16, QKV16 + BSD,
            nullptr, P16,
            DM, DM, SEQ, SD, SD, SS,
            0.03125f, DM, 1, 0, 0);
    }

    // 5) Causal softmax in place on fp16 P (+ zero fill to 128-boundary)
    softmax_causal<<<dim3(SEQ, BATCH), 256>>>(P16);

    // 6) O = P @ V (K truncated at diagonal; longest m-tiles issued FIRST)
    {
        dim3 g(DM / BN, SEQ / BM, BATCH);
        gemm_f16<<<g, NTHREADS, SMEM_TOTAL>>>(P16, Vt16,
            out, nullptr,
            SEQ, SEQ, DM, SS, SD, SD,
            1.f, SEQ, 0, 1, 1);
    }
}

// round 15
// speedup vs baseline: 1.1235x; 1.1235x over previous
#include <cuda_runtime.h>
#include <cuda_fp16.h>
#include <math_constants.h>
#include <cstdint>

#define BATCH 4
#define SEQ   2048
#define DM    1024

#define BM 128
#define BN 128
#define BK 32                      // fp16 per chunk (64 bytes per row)
#define STAGES 4
#define MAT_BYTES (128 * 64)       // 128x32 fp16 = 8192 B
#define STAGE_BYTES (2 * MAT_BYTES)        // A + B = 16384 B
#define SMEM_TOTAL (STAGES * STAGE_BYTES)  // 65536 B (x2 CTAs = 128 KB/SM)

// scores grid is 16x16 per batch; CTAs strictly above the diagonal are skipped:
#define SKIPPED_PER_BATCH 120              // 15+14+...+1
#define TOTAL_SKIPPED (SKIPPED_PER_BATCH * BATCH)   // 480
#define VT_TILES (BATCH * (SEQ / 64) * (DM / 64))   // 4*32*16 = 2048

// ---------------------------------------------------------------------------
// Scratch (allocation-free)
// ---------------------------------------------------------------------------
__device__ __half g_x16[(size_t)BATCH*SEQ*DM];
__device__ __half g_W16[(size_t)3*DM*DM];
__device__ __half g_QKV16[(size_t)3*BATCH*SEQ*DM];
__device__ __half g_Vt16[(size_t)BATCH*DM*SEQ];
__device__ __half g_P16[(size_t)BATCH*SEQ*SEQ];

// ---------------------------------------------------------------------------
// PTX helpers (base sm_80+ features only)
// ---------------------------------------------------------------------------
__device__ __forceinline__ uint32_t smem_u32(const void* p) {
    uint32_t a;
    asm("{ .reg .u64 t; cvta.to.shared.u64 t, %1; cvt.u32.u64 %0, t; }" : "=r"(a) : "l"(p));
    return a;
}
__device__ __forceinline__ void cp_async16(uint32_t s, const void* g) {
    asm volatile("cp.async.cg.shared.global [%0], [%1], 16;" :: "r"(s), "l"(g));
}
#define CP_COMMIT() asm volatile("cp.async.commit_group;" ::: "memory")
#define CP_WAIT2()  asm volatile("cp.async.wait_group 2;" ::: "memory")

__device__ __forceinline__ void ldmx4(uint32_t* r, uint32_t a) {
    asm volatile("ldmatrix.sync.aligned.m8n8.x4.shared.b16 {%0,%1,%2,%3}, [%4];"
        : "=r"(r[0]), "=r"(r[1]), "=r"(r[2]), "=r"(r[3]) : "r"(a));
}
__device__ __forceinline__ void mma16816(float* c, const uint32_t* a, const uint32_t* b) {
    asm volatile("mma.sync.aligned.m16n8k16.row.col.f32.f16.f16.f32 "
        "{%0,%1,%2,%3}, {%4,%5,%6,%7}, {%8,%9}, {%0,%1,%2,%3};"
        : "+f"(c[0]), "+f"(c[1]), "+f"(c[2]), "+f"(c[3])
        : "r"(a[0]), "r"(a[1]), "r"(a[2]), "r"(a[3]), "r"(b[0]), "r"(b[1]));
}

// Swizzled smem byte offset for (row, 16B-chunk c16) inside an Nx32-fp16 tile.
__device__ __forceinline__ uint32_t sw_off(int row, int c16) {
    return (uint32_t)(row * 64 + ((c16 ^ ((row >> 1) & 3)) << 4));
}

// ---------------------------------------------------------------------------
// fp16 NT GEMM via mma.sync: C[128,128] = A[M,K] @ B[N,K]^T, fp32 accumulate.
// Warp tile 64x32 (8 warps: 2M x 4N), 2 CTAs/SM. (Best measured config.)
// revM: reverse m-tile order (LPT schedule for causal-K truncated GEMM).
// Vsrc/Vt: when causalSkip, skipped CTAs transpose V [B][S][D] -> [B][D][S]
// instead of idling (free work inside the scores launch window).
// ---------------------------------------------------------------------------
__global__ __launch_bounds__(256, 2) void gemm_f16(
    const __half* __restrict__ A, const __half* __restrict__ B,
    float* __restrict__ outF, __half* __restrict__ outH,
    const __half* __restrict__ Vsrc, __half* __restrict__ Vt,
    int lda, int ldb, int ldc, long sA, long sB, long sC,
    float alpha, int Ktot, int causalSkip, int causalK, int revM)
{
    const int mTile = revM ? (int)(gridDim.y - 1 - blockIdx.y) : (int)blockIdx.y;
    const int m0 = mTile * BM;
    const int n0 = blockIdx.x * BN;

    extern __shared__ char smem[];

    if (causalSkip && n0 >= m0 + BM) {
        // ------- skipped-CTA duty: cooperative V transpose -------
        if (Vt) {
            const int mT = (int)blockIdx.y, nT = (int)blockIdx.x, z = (int)blockIdx.z;
            const int local = mT * 15 - (mT * (mT - 1)) / 2 + (nT - mT - 1);
            const int gid = z * SKIPPED_PER_BATCH + local;

            __half (*t)[65] = reinterpret_cast<__half(*)[65]>(smem);
            const int tx = threadIdx.x & 31, ty = threadIdx.x >> 5;

            for (int tt = gid; tt < VT_TILES; tt += TOTAL_SKIPPED) {
                const int b    = tt >> 9;          // 512 tiles per batch
                const int tile = tt & 511;
                const int n0t  = (tile & 15) * 64; // DM dim (16 tiles)
                const int k0t  = (tile >> 4) * 64; // SEQ dim (32 tiles)

                const __half* s = Vsrc + ((size_t)b * SEQ + k0t) * DM + n0t;
#pragma unroll
                for (int i = 0; i < 8; i++) {
                    const int r = ty + i * 8;
                    __half2 v = *(const __half2*)(s + (size_t)r * DM + 2 * tx);
                    t[r][2 * tx] = __low2half(v);
                    t[r][2 * tx + 1] = __high2half(v);
                }
                __syncthreads();
                __half* d = Vt + ((size_t)b * DM + n0t) * SEQ + k0t;
#pragma unroll
                for (int i = 0; i < 8; i++) {
                    const int rn = ty + i * 8;
                    *(__half2*)(d + (size_t)rn * SEQ + 2 * tx) =
                        __halves2half2(t[2 * tx][rn], t[2 * tx + 1][rn]);
                }
                __syncthreads();
            }
        }
        return;
    }

    const uint32_t sb = smem_u32(smem);

    const int tid  = threadIdx.x;
    const int lane = tid & 31;
    const int wid  = tid >> 5;
    const int warpM0 = (wid >> 2) * 64;   // 2 warps along M
    const int warpN0 = (wid & 3) * 32;    // 4 warps along N

    A += (size_t)blockIdx.z * sA;
    B += (size_t)blockIdx.z * sB;

    const int kEnd = causalK ? min(Ktot, m0 + BM) : Ktot;
    const int nCh = kEnd / BK;

    auto issue = [&](int c) {
        const uint32_t st = sb + (uint32_t)(c & (STAGES - 1)) * STAGE_BYTES;
        const int k0 = c * BK;
#pragma unroll
        for (int r = 0; r < 2; r++) {
            const int i = tid + r * 256;
            const int row = i >> 2, c16 = i & 3;
            const uint32_t so = sw_off(row, c16);
            cp_async16(st + so,             A + (size_t)(m0 + row) * lda + k0 + c16 * 8);
            cp_async16(st + MAT_BYTES + so, B + (size_t)(n0 + row) * ldb + k0 + c16 * 8);
        }
    };

    float acc[4][4][4];
#pragma unroll
    for (int i = 0; i < 4; i++)
#pragma unroll
        for (int j = 0; j < 4; j++)
#pragma unroll
            for (int k = 0; k < 4; k++) acc[i][j][k] = 0.f;

#pragma unroll
    for (int s = 0; s < STAGES - 1; s++) {
        if (s < nCh) issue(s);
        CP_COMMIT();
    }

    const int aRow = (lane & 15);
    const int aHi  = (lane >> 4);
    const int bRow = (lane & 7) + ((lane >> 4) << 3);   // B pair: n8 tile / tile+1
    const int bHi  = ((lane >> 3) & 1);

    for (int c = 0; c < nCh; c++) {
        CP_WAIT2();
        __syncthreads();
        if (c + STAGES - 1 < nCh) issue(c + STAGES - 1);
        CP_COMMIT();

        const uint32_t st = sb + (uint32_t)(c & (STAGES - 1)) * STAGE_BYTES;
#pragma unroll
        for (int ks = 0; ks < 2; ks++) {
            uint32_t af[4][4];
#pragma unroll
            for (int mf = 0; mf < 4; mf++)
                ldmx4(af[mf], st + sw_off(warpM0 + mf * 16 + aRow, ks * 2 + aHi));
#pragma unroll
            for (int nfp = 0; nfp < 2; nfp++) {
                uint32_t bh[4];
                ldmx4(bh, st + MAT_BYTES +
                      sw_off(warpN0 + nfp * 16 + bRow, ks * 2 + bHi));
#pragma unroll
                for (int mf = 0; mf < 4; mf++) {
                    mma16816(acc[mf][2*nfp],     af[mf], bh + 0);
                    mma16816(acc[mf][2*nfp + 1], af[mf], bh + 2);
                }
            }
        }
    }

    // epilogue
    const long cb = (long)blockIdx.z * sC;
    const int rBase = m0 + warpM0 + (lane >> 2);
    const int cBase = n0 + warpN0 + (lane & 3) * 2;
#pragma unroll
    for (int mf = 0; mf < 4; mf++) {
#pragma unroll
        for (int nf = 0; nf < 4; nf++) {
            const int col = cBase + nf * 8;
#pragma unroll
            for (int h = 0; h < 2; h++) {
                const int row = rBase + mf * 16 + h * 8;
                const float v0 = acc[mf][nf][2 * h] * alpha;
                const float v1 = acc[mf][nf][2 * h + 1] * alpha;
                if (outF) {
                    *(float2*)(outF + cb + (size_t)row * ldc + col) =
                        make_float2(v0, v1);
                } else {
                    *(__half2*)(outH + cb + (size_t)row * ldc + col) =
                        __floats2half2_rn(v0, v1);
                }
            }
        }
    }
}

// ---------------------------------------------------------------------------
// One fused fp32->fp16 convert for x, Wq, Wk, Wv.
// ---------------------------------------------------------------------------
#define XN4 (BATCH*SEQ*DM/4)
#define WN4 (DM*DM/4)
__global__ __launch_bounds__(256) void to_f16_all(
    const float* __restrict__ x, const float* __restrict__ Wq,
    const float* __restrict__ Wk, const float* __restrict__ Wv,
    __half* __restrict__ x16, __half* __restrict__ W16)
{
    int i = blockIdx.x * 256 + threadIdx.x;
    const float* src;
    __half* dst;
    int off;
    if (i < XN4) { src = x; dst = x16; off = i; }
    else {
        int j = i - XN4;
        int w = j / WN4;
        off = j - w * WN4;
        src = (w == 0) ? Wq : (w == 1) ? Wk : Wv;
        dst = W16 + (size_t)w * DM * DM;
        if (i >= XN4 + 3 * WN4) return;
    }
    float4 v = ((const float4*)src)[off];
    __half2* D = (__half2*)dst + 2 * (size_t)off;
    D[0] = __floats2half2_rn(v.x, v.y);
    D[1] = __floats2half2_rn(v.z, v.w);
}

// ---------------------------------------------------------------------------
// Causal softmax on one row (256 threads), fp16 in place.
// Zero-fills (len, roundup(len,128)) so PV's truncated K loop sees zeros.
// ---------------------------------------------------------------------------
__device__ void softmax_row(__half* row, int len, float* sred, float* sbc)
{
    const int tid = threadIdx.x;

    float vals[8]; int n = 0;
    float m = -CUDART_INF_F;
    for (int i = tid; i < len; i += 256) {
        float v = __half2float(row[i]);
        vals[n++] = v;
        m = fmaxf(m, v);
    }
#pragma unroll
    for (int o = 16; o; o >>= 1) m = fmaxf(m, __shfl_xor_sync(0xffffffffu, m, o));
    if ((tid & 31) == 0) sred[tid >> 5] = m;
    __syncthreads();
    if (tid == 0) {
        float t = sred[0];
#pragma unroll
        for (int w = 1; w < 8; w++) t = fmaxf(t, sred[w]);
        *sbc = t;
    }
    __syncthreads();
    m = *sbc;

    float s = 0.f;
#pragma unroll
    for (int k = 0; k < 8; k++)
        if (k < n) { float e = expf(vals[k] - m); vals[k] = e; s += e; }
#pragma unroll
    for (int o = 16; o; o >>= 1) s += __shfl_xor_sync(0xffffffffu, s, o);
    __syncthreads();
    if ((tid & 31) == 0) sred[tid >> 5] = s;
    __syncthreads();
    if (tid == 0) {
        float t = 0.f;
#pragma unroll
        for (int w = 0; w < 8; w++) t += sred[w];
        *sbc = 1.f / t;
    }
    __syncthreads();
    const float inv = *sbc;

    n = 0;
    for (int i = tid; i < len; i += 256) row[i] = __float2half_rn(vals[n++] * inv);

    const __half z = __float2half_rn(0.f);
    const int tileEnd = ((len + 127) >> 7) << 7;   // roundup(len,128)
    for (int i = len + tid; i < tileEnd; i += 256) row[i] = z;
}

// Paired rows q and SEQ-1-q -> constant work (2049) per block, 4096 blocks total.
__global__ __launch_bounds__(256) void softmax_causal2(__half* __restrict__ P16)
{
    const int q1 = blockIdx.x;            // 0..1023
    const int q2 = SEQ - 1 - q1;          // 2047..1024
    const int b  = blockIdx.y;

    __shared__ float sred[8];
    __shared__ float sbc;

    softmax_row(P16 + ((size_t)b * SEQ + q1) * SEQ, q1 + 1, sred, &sbc);
    __syncthreads();
    softmax_row(P16 + ((size_t)b * SEQ + q2) * SEQ, q2 + 1, sred, &sbc);
}

// ---------------------------------------------------------------------------
extern "C" void kernel_launch(void* const* d_in, const int* in_sizes, int n_in,
                              void* d_out, int out_size)
{
    const float* x  = (const float*)d_in[0];
    const float* Wq = (const float*)d_in[1];
    const float* Wk = (const float*)d_in[2];
    const float* Wv = (const float*)d_in[3];
    float* out = (float*)d_out;

    __half *x16, *W16, *QKV16, *Vt16, *P16;
    cudaGetSymbolAddress((void**)&x16, g_x16);
    cudaGetSymbolAddress((void**)&W16, g_W16);
    cudaGetSymbolAddress((void**)&QKV16, g_QKV16);
    cudaGetSymbolAddress((void**)&Vt16, g_Vt16);
    cudaGetSymbolAddress((void**)&P16, g_P16);

    const long BSD = (long)BATCH * SEQ * DM;
    const long SD  = (long)SEQ * DM;
    const long SS  = (long)SEQ * SEQ;

    cudaFuncSetAttribute(gemm_f16, cudaFuncAttributeMaxDynamicSharedMemorySize, SMEM_TOTAL);

    // 1) fused fp32 -> fp16 conversion (x + Wq + Wk + Wv)
    {
        const int total = XN4 + 3 * WN4;
        to_f16_all<<<(total + 255) / 256, 256>>>(x, Wq, Wk, Wv, x16, W16);
    }

    // 2) Fused QKV projection (z selects weight + output section; A fixed)
    {
        dim3 g(DM / BN, (BATCH * SEQ) / BM, 3);
        gemm_f16<<<g, 256, SMEM_TOTAL>>>(x16, W16,
            nullptr, QKV16, nullptr, nullptr,
            DM, DM, DM, 0, (long)DM * DM, BSD,
            1.f, DM, 0, 0, 0);
    }

    // 3) Scores -> fp16 P (causal tile skip); skipped CTAs transpose V -> V^T
    {
        dim3 g(SEQ / BN, SEQ / BM, BATCH);
        gemm_f16<<<g, 256, SMEM_TOTAL>>>(QKV16, QKV16 + BSD,
            nullptr, P16, QKV16 + 2 * BSD, Vt16,
            DM, DM, SEQ, SD, SD, SS,
            0.03125f, DM, 1, 0, 0);
    }

    // 4) Causal softmax in place on fp16 P (paired rows, balanced blocks)
    softmax_causal2<<<dim3(SEQ / 2, BATCH), 256>>>(P16);

    // 5) O = P @ V (K truncated at diagonal; longest m-tiles issued FIRST)
    {
        dim3 g(DM / BN, SEQ / BM, BATCH);
        gemm_f16<<<g, 256, SMEM_TOTAL>>>(P16, Vt16,
            out, nullptr, nullptr, nullptr,
            SEQ, SEQ, DM, SS, SD, SD,
            1.f, SEQ, 0, 1, 1);
    }
}

// round 16
// speedup vs baseline: 1.1242x; 1.0006x over previous
#include <cuda_runtime.h>
#include <cuda_fp16.h>
#include <math_constants.h>
#include <cstdint>

#define BATCH 4
#define SEQ   2048
#define DM    1024

#define BM 128
#define BN 128
#define BK 32                      // fp16 per chunk (64 bytes per row)
#define STAGES 4
#define MAT_BYTES (128 * 64)       // 128x32 fp16 = 8192 B
#define STAGE_BYTES (2 * MAT_BYTES)        // A + B = 16384 B
#define SMEM_TOTAL (STAGES * STAGE_BYTES)  // 65536 B (x2 CTAs = 128 KB/SM)

// scores grid is 16x16 per batch; CTAs strictly above the diagonal are skipped:
#define SKIPPED_PER_BATCH 120              // 15+14+...+1
#define TOTAL_SKIPPED (SKIPPED_PER_BATCH * BATCH)   // 480
#define VT_TILES (BATCH * (SEQ / 64) * (DM / 64))   // 4*32*16 = 2048

// ---------------------------------------------------------------------------
// Scratch (allocation-free)
// ---------------------------------------------------------------------------
__device__ __half g_x16[(size_t)BATCH*SEQ*DM];
__device__ __half g_W16[(size_t)3*DM*DM];
__device__ __half g_QKV16[(size_t)3*BATCH*SEQ*DM];
__device__ __half g_Vt16[(size_t)BATCH*DM*SEQ];
__device__ __half g_P16[(size_t)BATCH*SEQ*SEQ];
__device__ float  g_invS[(size_t)BATCH*SEQ];

// ---------------------------------------------------------------------------
// PTX helpers (base sm_80+ features only)
// ---------------------------------------------------------------------------
__device__ __forceinline__ uint32_t smem_u32(const void* p) {
    uint32_t a;
    asm("{ .reg .u64 t; cvta.to.shared.u64 t, %1; cvt.u32.u64 %0, t; }" : "=r"(a) : "l"(p));
    return a;
}
__device__ __forceinline__ void cp_async16(uint32_t s, const void* g) {
    asm volatile("cp.async.cg.shared.global [%0], [%1], 16;" :: "r"(s), "l"(g));
}
#define CP_COMMIT() asm volatile("cp.async.commit_group;" ::: "memory")
#define CP_WAIT2()  asm volatile("cp.async.wait_group 2;" ::: "memory")

__device__ __forceinline__ void ldmx4(uint32_t* r, uint32_t a) {
    asm volatile("ldmatrix.sync.aligned.m8n8.x4.shared.b16 {%0,%1,%2,%3}, [%4];"
        : "=r"(r[0]), "=r"(r[1]), "=r"(r[2]), "=r"(r[3]) : "r"(a));
}
__device__ __forceinline__ void mma16816(float* c, const uint32_t* a, const uint32_t* b) {
    asm volatile("mma.sync.aligned.m16n8k16.row.col.f32.f16.f16.f32 "
        "{%0,%1,%2,%3}, {%4,%5,%6,%7}, {%8,%9}, {%0,%1,%2,%3};"
        : "+f"(c[0]), "+f"(c[1]), "+f"(c[2]), "+f"(c[3])
        : "r"(a[0]), "r"(a[1]), "r"(a[2]), "r"(a[3]), "r"(b[0]), "r"(b[1]));
}

// Swizzled smem byte offset for (row, 16B-chunk c16) inside an Nx32-fp16 tile.
__device__ __forceinline__ uint32_t sw_off(int row, int c16) {
    return (uint32_t)(row * 64 + ((c16 ^ ((row >> 1) & 3)) << 4));
}

// ---------------------------------------------------------------------------
// fp16 NT GEMM via mma.sync: C[128,128] = A[M,K] @ B[N,K]^T, fp32 accumulate.
// Warp tile 64x32 (8 warps: 2M x 4N), 2 CTAs/SM.
// revM: reverse m-tile order (LPT schedule for causal-K truncated GEMM).
// doExp: apply __expf to outputs (scores -> unnormalized softmax numerators).
// rowScale: per-output-row fp32 scale (PV normalization), indexed z*SEQ+row.
// Vsrc/Vt: when causalSkip, skipped CTAs transpose V [B][S][D] -> [B][D][S].
// ---------------------------------------------------------------------------
__global__ __launch_bounds__(256, 2) void gemm_f16(
    const __half* __restrict__ A, const __half* __restrict__ B,
    float* __restrict__ outF, __half* __restrict__ outH,
    const __half* __restrict__ Vsrc, __half* __restrict__ Vt,
    const float* __restrict__ rowScale,
    int lda, int ldb, int ldc, long sA, long sB, long sC,
    float alpha, int Ktot, int causalSkip, int causalK, int revM, int doExp)
{
    const int mTile = revM ? (int)(gridDim.y - 1 - blockIdx.y) : (int)blockIdx.y;
    const int m0 = mTile * BM;
    const int n0 = blockIdx.x * BN;

    extern __shared__ char smem[];

    if (causalSkip && n0 >= m0 + BM) {
        // ------- skipped-CTA duty: cooperative V transpose -------
        if (Vt) {
            const int mT = (int)blockIdx.y, nT = (int)blockIdx.x, z = (int)blockIdx.z;
            const int local = mT * 15 - (mT * (mT - 1)) / 2 + (nT - mT - 1);
            const int gid = z * SKIPPED_PER_BATCH + local;

            __half (*t)[65] = reinterpret_cast<__half(*)[65]>(smem);
            const int tx = threadIdx.x & 31, ty = threadIdx.x >> 5;

            for (int tt = gid; tt < VT_TILES; tt += TOTAL_SKIPPED) {
                const int b    = tt >> 9;
                const int tile = tt & 511;
                const int n0t  = (tile & 15) * 64;
                const int k0t  = (tile >> 4) * 64;

                const __half* s = Vsrc + ((size_t)b * SEQ + k0t) * DM + n0t;
#pragma unroll
                for (int i = 0; i < 8; i++) {
                    const int r = ty + i * 8;
                    __half2 v = *(const __half2*)(s + (size_t)r * DM + 2 * tx);
                    t[r][2 * tx] = __low2half(v);
                    t[r][2 * tx + 1] = __high2half(v);
                }
                __syncthreads();
                __half* d = Vt + ((size_t)b * DM + n0t) * SEQ + k0t;
#pragma unroll
                for (int i = 0; i < 8; i++) {
                    const int rn = ty + i * 8;
                    *(__half2*)(d + (size_t)rn * SEQ + 2 * tx) =
                        __halves2half2(t[2 * tx][rn], t[2 * tx + 1][rn]);
                }
                __syncthreads();
            }
        }
        return;
    }

    const uint32_t sb = smem_u32(smem);

    const int tid  = threadIdx.x;
    const int lane = tid & 31;
    const int wid  = tid >> 5;
    const int warpM0 = (wid >> 2) * 64;
    const int warpN0 = (wid & 3) * 32;

    A += (size_t)blockIdx.z * sA;
    B += (size_t)blockIdx.z * sB;

    const int kEnd = causalK ? min(Ktot, m0 + BM) : Ktot;
    const int nCh = kEnd / BK;

    auto issue = [&](int c) {
        const uint32_t st = sb + (uint32_t)(c & (STAGES - 1)) * STAGE_BYTES;
        const int k0 = c * BK;
#pragma unroll
        for (int r = 0; r < 2; r++) {
            const int i = tid + r * 256;
            const int row = i >> 2, c16 = i & 3;
            const uint32_t so = sw_off(row, c16);
            cp_async16(st + so,             A + (size_t)(m0 + row) * lda + k0 + c16 * 8);
            cp_async16(st + MAT_BYTES + so, B + (size_t)(n0 + row) * ldb + k0 + c16 * 8);
        }
    };

    float acc[4][4][4];
#pragma unroll
    for (int i = 0; i < 4; i++)
#pragma unroll
        for (int j = 0; j < 4; j++)
#pragma unroll
            for (int k = 0; k < 4; k++) acc[i][j][k] = 0.f;

#pragma unroll
    for (int s = 0; s < STAGES - 1; s++) {
        if (s < nCh) issue(s);
        CP_COMMIT();
    }

    const int aRow = (lane & 15);
    const int aHi  = (lane >> 4);
    const int bRow = (lane & 7) + ((lane >> 4) << 3);
    const int bHi  = ((lane >> 3) & 1);

    for (int c = 0; c < nCh; c++) {
        CP_WAIT2();
        __syncthreads();
        if (c + STAGES - 1 < nCh) issue(c + STAGES - 1);
        CP_COMMIT();

        const uint32_t st = sb + (uint32_t)(c & (STAGES - 1)) * STAGE_BYTES;
#pragma unroll
        for (int ks = 0; ks < 2; ks++) {
            uint32_t af[4][4];
#pragma unroll
            for (int mf = 0; mf < 4; mf++)
                ldmx4(af[mf], st + sw_off(warpM0 + mf * 16 + aRow, ks * 2 + aHi));
#pragma unroll
            for (int nfp = 0; nfp < 2; nfp++) {
                uint32_t bh[4];
                ldmx4(bh, st + MAT_BYTES +
                      sw_off(warpN0 + nfp * 16 + bRow, ks * 2 + bHi));
#pragma unroll
                for (int mf = 0; mf < 4; mf++) {
                    mma16816(acc[mf][2*nfp],     af[mf], bh + 0);
                    mma16816(acc[mf][2*nfp + 1], af[mf], bh + 2);
                }
            }
        }
    }

    // epilogue
    const long cb = (long)blockIdx.z * sC;
    const int rBase = m0 + warpM0 + (lane >> 2);
    const int cBase = n0 + warpN0 + (lane & 3) * 2;
#pragma unroll
    for (int mf = 0; mf < 4; mf++) {
#pragma unroll
        for (int h = 0; h < 2; h++) {
            const int row = rBase + mf * 16 + h * 8;
            const float rs = rowScale
                ? rowScale[(size_t)blockIdx.z * SEQ + row] : alpha;
#pragma unroll
            for (int nf = 0; nf < 4; nf++) {
                const int col = cBase + nf * 8;
                float v0 = acc[mf][nf][2 * h] * rs;
                float v1 = acc[mf][nf][2 * h + 1] * rs;
                if (outF) {
                    *(float2*)(outF + cb + (size_t)row * ldc + col) =
                        make_float2(v0, v1);
                } else {
                    if (doExp) { v0 = __expf(v0); v1 = __expf(v1); }
                    *(__half2*)(outH + cb + (size_t)row * ldc + col) =
                        __floats2half2_rn(v0, v1);
                }
            }
        }
    }
}

// ---------------------------------------------------------------------------
// One fused fp32->fp16 convert for x, Wq, Wk, Wv.
// ---------------------------------------------------------------------------
#define XN4 (BATCH*SEQ*DM/4)
#define WN4 (DM*DM/4)
__global__ __launch_bounds__(256) void to_f16_all(
    const float* __restrict__ x, const float* __restrict__ Wq,
    const float* __restrict__ Wk, const float* __restrict__ Wv,
    __half* __restrict__ x16, __half* __restrict__ W16)
{
    int i = blockIdx.x * 256 + threadIdx.x;
    const float* src;
    __half* dst;
    int off;
    if (i < XN4) { src = x; dst = x16; off = i; }
    else {
        int j = i - XN4;
        int w = j / WN4;
        off = j - w * WN4;
        src = (w == 0) ? Wq : (w == 1) ? Wk : Wv;
        dst = W16 + (size_t)w * DM * DM;
        if (i >= XN4 + 3 * WN4) return;
    }
    float4 v = ((const float4*)src)[off];
    __half2* D = (__half2*)dst + 2 * (size_t)off;
    D[0] = __floats2half2_rn(v.x, v.y);
    D[1] = __floats2half2_rn(v.z, v.w);
}

// ---------------------------------------------------------------------------
// Row-sum of exp values (already stored in P), one row per block:
// invS[row] = 1 / sum_{k<=q} P[k]; zero-fill (q, roundup(q+1,128)).
// Sum is computed from the fp16-rounded stored values so normalization is
// exactly consistent with what the PV GEMM reads.
// ---------------------------------------------------------------------------
__global__ __launch_bounds__(256) void rowsum_inv(
    __half* __restrict__ P16, float* __restrict__ invS)
{
    const int q = blockIdx.x, b = blockIdx.y;
    __half* row = P16 + ((size_t)b * SEQ + q) * SEQ;
    const int len = q + 1, tid = threadIdx.x;

    __shared__ float sred[8];

    float s = 0.f;
    for (int i = tid; i < len; i += 256) s += __half2float(row[i]);
#pragma unroll
    for (int o = 16; o; o >>= 1) s += __shfl_xor_sync(0xffffffffu, s, o);
    if ((tid & 31) == 0) sred[tid >> 5] = s;
    __syncthreads();

    if (tid == 0) {
        float t = 0.f;
#pragma unroll
        for (int w = 0; w < 8; w++) t += sred[w];
        invS[(size_t)b * SEQ + q] = 1.f / t;
    }

    const __half z = __float2half_rn(0.f);
    const int tileEnd = ((q >> 7) + 1) << 7;   // roundup(q+1, 128)
    for (int i = len + tid; i < tileEnd; i += 256) row[i] = z;
}

// ---------------------------------------------------------------------------
extern "C" void kernel_launch(void* const* d_in, const int* in_sizes, int n_in,
                              void* d_out, int out_size)
{
    const float* x  = (const float*)d_in[0];
    const float* Wq = (const float*)d_in[1];
    const float* Wk = (const float*)d_in[2];
    const float* Wv = (const float*)d_in[3];
    float* out = (float*)d_out;

    __half *x16, *W16, *QKV16, *Vt16, *P16;
    float* invS;
    cudaGetSymbolAddress((void**)&x16, g_x16);
    cudaGetSymbolAddress((void**)&W16, g_W16);
    cudaGetSymbolAddress((void**)&QKV16, g_QKV16);
    cudaGetSymbolAddress((void**)&Vt16, g_Vt16);
    cudaGetSymbolAddress((void**)&P16, g_P16);
    cudaGetSymbolAddress((void**)&invS, g_invS);

    const long BSD = (long)BATCH * SEQ * DM;
    const long SD  = (long)SEQ * DM;
    const long SS  = (long)SEQ * SEQ;

    cudaFuncSetAttribute(gemm_f16, cudaFuncAttributeMaxDynamicSharedMemorySize, SMEM_TOTAL);

    // 1) fused fp32 -> fp16 conversion (x + Wq + Wk + Wv)
    {
        const int total = XN4 + 3 * WN4;
        to_f16_all<<<(total + 255) / 256, 256>>>(x, Wq, Wk, Wv, x16, W16);
    }

    // 2) Fused QKV projection (z selects weight + output section; A fixed)
    {
        dim3 g(DM / BN, (BATCH * SEQ) / BM, 3);
        gemm_f16<<<g, 256, SMEM_TOTAL>>>(x16, W16,
            nullptr, QKV16, nullptr, nullptr, nullptr,
            DM, DM, DM, 0, (long)DM * DM, BSD,
            1.f, DM, 0, 0, 0, 0);
    }

    // 3) Scores -> P = exp((1/32) Q K^T), unnormalized, fp16.
    //    Causal tile skip; skipped CTAs transpose V -> V^T.
    {
        dim3 g(SEQ / BN, SEQ / BM, BATCH);
        gemm_f16<<<g, 256, SMEM_TOTAL>>>(QKV16, QKV16 + BSD,
            nullptr, P16, QKV16 + 2 * BSD, Vt16, nullptr,
            DM, DM, SEQ, SD, SD, SS,
            0.03125f, DM, 1, 0, 0, 1);
    }

    // 4) Row sums -> invS; zero-fill masked remainder of diagonal tiles
    rowsum_inv<<<dim3(SEQ, BATCH), 256>>>(P16, invS);

    // 5) O = (P @ V) * invS[row]  (K truncated at diagonal; LPT order)
    {
        dim3 g(DM / BN, SEQ / BM, BATCH);
        gemm_f16<<<g, 256, SMEM_TOTAL>>>(P16, Vt16,
            out, nullptr, nullptr, nullptr, invS,
            SEQ, SEQ, DM, SS, SD, SD,
            1.f, SEQ, 0, 1, 1, 0);
    }
}

// round 17
// speedup vs baseline: 1.1792x; 1.0490x over previous
#include <cuda_runtime.h>
#include <cuda_fp16.h>
#include <math_constants.h>
#include <cstdint>

#define BATCH 4
#define SEQ   2048
#define DM    1024

#define BM 128
#define BN 128
#define BK 32                      // fp16 per chunk (64 bytes per row)
#define STAGES 4
#define MAT_BYTES (128 * 64)       // 128x32 fp16 = 8192 B
#define STAGE_BYTES (2 * MAT_BYTES)        // A + B = 16384 B
#define SMEM_TOTAL (STAGES * STAGE_BYTES)  // 65536 B (x2 CTAs = 128 KB/SM)

// scores grid is 16x16 per batch; CTAs strictly above the diagonal are skipped:
#define SKIPPED_PER_BATCH 120              // 15+14+...+1
#define TOTAL_SKIPPED (SKIPPED_PER_BATCH * BATCH)   // 480
#define VT_TILES (BATCH * (SEQ / 64) * (DM / 64))   // 4*32*16 = 2048

// ---------------------------------------------------------------------------
// Scratch (allocation-free)
// ---------------------------------------------------------------------------
__device__ __half g_x16[(size_t)BATCH*SEQ*DM];
__device__ __half g_W16[(size_t)3*DM*DM];
__device__ __half g_QKV16[(size_t)3*BATCH*SEQ*DM];
__device__ __half g_Vt16[(size_t)BATCH*DM*SEQ];
__device__ __half g_P16[(size_t)BATCH*SEQ*SEQ];
__device__ float  g_S[(size_t)BATCH*SEQ];   // unnormalized softmax row sums

// ---------------------------------------------------------------------------
// PTX helpers (base sm_80+ features only)
// ---------------------------------------------------------------------------
__device__ __forceinline__ uint32_t smem_u32(const void* p) {
    uint32_t a;
    asm("{ .reg .u64 t; cvta.to.shared.u64 t, %1; cvt.u32.u64 %0, t; }" : "=r"(a) : "l"(p));
    return a;
}
__device__ __forceinline__ void cp_async16(uint32_t s, const void* g) {
    asm volatile("cp.async.cg.shared.global [%0], [%1], 16;" :: "r"(s), "l"(g));
}
#define CP_COMMIT() asm volatile("cp.async.commit_group;" ::: "memory")
#define CP_WAIT2()  asm volatile("cp.async.wait_group 2;" ::: "memory")

__device__ __forceinline__ void ldmx4(uint32_t* r, uint32_t a) {
    asm volatile("ldmatrix.sync.aligned.m8n8.x4.shared.b16 {%0,%1,%2,%3}, [%4];"
        : "=r"(r[0]), "=r"(r[1]), "=r"(r[2]), "=r"(r[3]) : "r"(a));
}
__device__ __forceinline__ void mma16816(float* c, const uint32_t* a, const uint32_t* b) {
    asm volatile("mma.sync.aligned.m16n8k16.row.col.f32.f16.f16.f32 "
        "{%0,%1,%2,%3}, {%4,%5,%6,%7}, {%8,%9}, {%0,%1,%2,%3};"
        : "+f"(c[0]), "+f"(c[1]), "+f"(c[2]), "+f"(c[3])
        : "r"(a[0]), "r"(a[1]), "r"(a[2]), "r"(a[3]), "r"(b[0]), "r"(b[1]));
}

// Swizzled smem byte offset for (row, 16B-chunk c16) inside an Nx32-fp16 tile.
__device__ __forceinline__ uint32_t sw_off(int row, int c16) {
    return (uint32_t)(row * 64 + ((c16 ^ ((row >> 1) & 3)) << 4));
}

// ---------------------------------------------------------------------------
// fp16 NT GEMM via mma.sync: C[128,128] = A[M,K] @ B[N,K]^T, fp32 accumulate.
// Warp tile 64x32 (8 warps: 2M x 4N), 2 CTAs/SM.
// revM: reverse m-tile order (LPT schedule for causal-K truncated GEMM).
// doExp + sumOut: scores mode -- outputs exp(acc*alpha) in fp16, masks
//   col > row on diagonal tiles to exact zero, and atomically accumulates
//   per-row sums into sumOut[z*SEQ+row].
// rowScale: PV mode -- multiply output row by 1/rowScale[z*SEQ+row].
// Vsrc/Vt: when causalSkip, skipped CTAs transpose V [B][S][D] -> [B][D][S].
// ---------------------------------------------------------------------------
__global__ __launch_bounds__(256, 2) void gemm_f16(
    const __half* __restrict__ A, const __half* __restrict__ B,
    float* __restrict__ outF, __half* __restrict__ outH,
    const __half* __restrict__ Vsrc, __half* __restrict__ Vt,
    const float* __restrict__ rowScale, float* __restrict__ sumOut,
    int lda, int ldb, int ldc, long sA, long sB, long sC,
    float alpha, int Ktot, int causalSkip, int causalK, int revM, int doExp)
{
    const int mTile = revM ? (int)(gridDim.y - 1 - blockIdx.y) : (int)blockIdx.y;
    const int m0 = mTile * BM;
    const int n0 = blockIdx.x * BN;

    extern __shared__ char smem[];

    if (causalSkip && n0 >= m0 + BM) {
        // ------- skipped-CTA duty: cooperative V transpose -------
        if (Vt) {
            const int mT = (int)blockIdx.y, nT = (int)blockIdx.x, z = (int)blockIdx.z;
            const int local = mT * 15 - (mT * (mT - 1)) / 2 + (nT - mT - 1);
            const int gid = z * SKIPPED_PER_BATCH + local;

            __half (*t)[65] = reinterpret_cast<__half(*)[65]>(smem);
            const int tx = threadIdx.x & 31, ty = threadIdx.x >> 5;

            for (int tt = gid; tt < VT_TILES; tt += TOTAL_SKIPPED) {
                const int b    = tt >> 9;
                const int tile = tt & 511;
                const int n0t  = (tile & 15) * 64;
                const int k0t  = (tile >> 4) * 64;

                const __half* s = Vsrc + ((size_t)b * SEQ + k0t) * DM + n0t;
#pragma unroll
                for (int i = 0; i < 8; i++) {
                    const int r = ty + i * 8;
                    __half2 v = *(const __half2*)(s + (size_t)r * DM + 2 * tx);
                    t[r][2 * tx] = __low2half(v);
                    t[r][2 * tx + 1] = __high2half(v);
                }
                __syncthreads();
                __half* d = Vt + ((size_t)b * DM + n0t) * SEQ + k0t;
#pragma unroll
                for (int i = 0; i < 8; i++) {
                    const int rn = ty + i * 8;
                    *(__half2*)(d + (size_t)rn * SEQ + 2 * tx) =
                        __halves2half2(t[2 * tx][rn], t[2 * tx + 1][rn]);
                }
                __syncthreads();
            }
        }
        return;
    }

    const uint32_t sb = smem_u32(smem);

    const int tid  = threadIdx.x;
    const int lane = tid & 31;
    const int wid  = tid >> 5;
    const int warpM0 = (wid >> 2) * 64;
    const int warpN0 = (wid & 3) * 32;

    A += (size_t)blockIdx.z * sA;
    B += (size_t)blockIdx.z * sB;

    const int kEnd = causalK ? min(Ktot, m0 + BM) : Ktot;
    const int nCh = kEnd / BK;

    auto issue = [&](int c) {
        const uint32_t st = sb + (uint32_t)(c & (STAGES - 1)) * STAGE_BYTES;
        const int k0 = c * BK;
#pragma unroll
        for (int r = 0; r < 2; r++) {
            const int i = tid + r * 256;
            const int row = i >> 2, c16 = i & 3;
            const uint32_t so = sw_off(row, c16);
            cp_async16(st + so,             A + (size_t)(m0 + row) * lda + k0 + c16 * 8);
            cp_async16(st + MAT_BYTES + so, B + (size_t)(n0 + row) * ldb + k0 + c16 * 8);
        }
    };

    float acc[4][4][4];
#pragma unroll
    for (int i = 0; i < 4; i++)
#pragma unroll
        for (int j = 0; j < 4; j++)
#pragma unroll
            for (int k = 0; k < 4; k++) acc[i][j][k] = 0.f;

#pragma unroll
    for (int s = 0; s < STAGES - 1; s++) {
        if (s < nCh) issue(s);
        CP_COMMIT();
    }

    const int aRow = (lane & 15);
    const int aHi  = (lane >> 4);
    const int bRow = (lane & 7) + ((lane >> 4) << 3);
    const int bHi  = ((lane >> 3) & 1);

    for (int c = 0; c < nCh; c++) {
        CP_WAIT2();
        __syncthreads();
        if (c + STAGES - 1 < nCh) issue(c + STAGES - 1);
        CP_COMMIT();

        const uint32_t st = sb + (uint32_t)(c & (STAGES - 1)) * STAGE_BYTES;
#pragma unroll
        for (int ks = 0; ks < 2; ks++) {
            uint32_t af[4][4];
#pragma unroll
            for (int mf = 0; mf < 4; mf++)
                ldmx4(af[mf], st + sw_off(warpM0 + mf * 16 + aRow, ks * 2 + aHi));
#pragma unroll
            for (int nfp = 0; nfp < 2; nfp++) {
                uint32_t bh[4];
                ldmx4(bh, st + MAT_BYTES +
                      sw_off(warpN0 + nfp * 16 + bRow, ks * 2 + bHi));
#pragma unroll
                for (int mf = 0; mf < 4; mf++) {
                    mma16816(acc[mf][2*nfp],     af[mf], bh + 0);
                    mma16816(acc[mf][2*nfp + 1], af[mf], bh + 2);
                }
            }
        }
    }

    // epilogue
    const long cb = (long)blockIdx.z * sC;
    const int rBase = m0 + warpM0 + (lane >> 2);
    const int cBase = n0 + warpN0 + (lane & 3) * 2;
    const bool diag = causalSkip && (n0 == m0);   // tile straddles the diagonal

#pragma unroll
    for (int mf = 0; mf < 4; mf++) {
#pragma unroll
        for (int h = 0; h < 2; h++) {
            const int row = rBase + mf * 16 + h * 8;
            float rsum = 0.f;
            float rs = alpha;
            if (rowScale) rs = 1.f / rowScale[(size_t)blockIdx.z * SEQ + row];
#pragma unroll
            for (int nf = 0; nf < 4; nf++) {
                const int col = cBase + nf * 8;
                float v0 = acc[mf][nf][2 * h] * rs;
                float v1 = acc[mf][nf][2 * h + 1] * rs;
                if (outF) {
                    *(float2*)(outF + cb + (size_t)row * ldc + col) =
                        make_float2(v0, v1);
                } else {
                    if (doExp) {
                        v0 = __expf(v0); v1 = __expf(v1);
                        if (diag) {
                            if (col > row)     v0 = 0.f;
                            if (col + 1 > row) v1 = 0.f;
                        }
                        rsum += v0 + v1;
                    }
                    *(__half2*)(outH + cb + (size_t)row * ldc + col) =
                        __floats2half2_rn(v0, v1);
                }
            }
            if (sumOut) {
                rsum += __shfl_xor_sync(0xffffffffu, rsum, 1);
                rsum += __shfl_xor_sync(0xffffffffu, rsum, 2);
                if ((lane & 3) == 0)
                    atomicAdd(sumOut + (size_t)blockIdx.z * SEQ + row, rsum);
            }
        }
    }
}

// ---------------------------------------------------------------------------
// One fused fp32->fp16 convert for x, Wq, Wk, Wv.
// ---------------------------------------------------------------------------
#define XN4 (BATCH*SEQ*DM/4)
#define WN4 (DM*DM/4)
__global__ __launch_bounds__(256) void to_f16_all(
    const float* __restrict__ x, const float* __restrict__ Wq,
    const float* __restrict__ Wk, const float* __restrict__ Wv,
    __half* __restrict__ x16, __half* __restrict__ W16)
{
    int i = blockIdx.x * 256 + threadIdx.x;
    const float* src;
    __half* dst;
    int off;
    if (i < XN4) { src = x; dst = x16; off = i; }
    else {
        int j = i - XN4;
        int w = j / WN4;
        off = j - w * WN4;
        src = (w == 0) ? Wq : (w == 1) ? Wk : Wv;
        dst = W16 + (size_t)w * DM * DM;
        if (i >= XN4 + 3 * WN4) return;
    }
    float4 v = ((const float4*)src)[off];
    __half2* D = (__half2*)dst + 2 * (size_t)off;
    D[0] = __floats2half2_rn(v.x, v.y);
    D[1] = __floats2half2_rn(v.z, v.w);
}

// ---------------------------------------------------------------------------
extern "C" void kernel_launch(void* const* d_in, const int* in_sizes, int n_in,
                              void* d_out, int out_size)
{
    const float* x  = (const float*)d_in[0];
    const float* Wq = (const float*)d_in[1];
    const float* Wk = (const float*)d_in[2];
    const float* Wv = (const float*)d_in[3];
    float* out = (float*)d_out;

    __half *x16, *W16, *QKV16, *Vt16, *P16;
    float* S;
    cudaGetSymbolAddress((void**)&x16, g_x16);
    cudaGetSymbolAddress((void**)&W16, g_W16);
    cudaGetSymbolAddress((void**)&QKV16, g_QKV16);
    cudaGetSymbolAddress((void**)&Vt16, g_Vt16);
    cudaGetSymbolAddress((void**)&P16, g_P16);
    cudaGetSymbolAddress((void**)&S, g_S);

    const long BSD = (long)BATCH * SEQ * DM;
    const long SD  = (long)SEQ * DM;
    const long SS  = (long)SEQ * SEQ;

    cudaFuncSetAttribute(gemm_f16, cudaFuncAttributeMaxDynamicSharedMemorySize, SMEM_TOTAL);

    // 0) zero the softmax-sum accumulator (graph-capturable, no allocation)
    cudaMemsetAsync(S, 0, (size_t)BATCH * SEQ * sizeof(float), 0);

    // 1) fused fp32 -> fp16 conversion (x + Wq + Wk + Wv)
    {
        const int total = XN4 + 3 * WN4;
        to_f16_all<<<(total + 255) / 256, 256>>>(x, Wq, Wk, Wv, x16, W16);
    }

    // 2) Fused QKV projection (z selects weight + output section; A fixed)
    {
        dim3 g(DM / BN, (BATCH * SEQ) / BM, 3);
        gemm_f16<<<g, 256, SMEM_TOTAL>>>(x16, W16,
            nullptr, QKV16, nullptr, nullptr, nullptr, nullptr,
            DM, DM, DM, 0, (long)DM * DM, BSD,
            1.f, DM, 0, 0, 0, 0);
    }

    // 3) Scores -> P = exp((1/32) Q K^T) fp16, diagonal masked to zero,
    //    per-row sums accumulated into S. Skipped CTAs transpose V -> V^T.
    {
        dim3 g(SEQ / BN, SEQ / BM, BATCH);
        gemm_f16<<<g, 256, SMEM_TOTAL>>>(QKV16, QKV16 + BSD,
            nullptr, P16, QKV16 + 2 * BSD, Vt16, nullptr, S,
            DM, DM, SEQ, SD, SD, SS,
            0.03125f, DM, 1, 0, 0, 1);
    }

    // 4) O = (P @ V) / S[row]  (K truncated at diagonal; LPT order)
    {
        dim3 g(DM / BN, SEQ / BM, BATCH);
        gemm_f16<<<g, 256, SMEM_TOTAL>>>(P16, Vt16,
            out, nullptr, nullptr, nullptr, S, nullptr,
            SEQ, SEQ, DM, SS, SD, SD,
            1.f, SEQ, 0, 1, 1, 0);
    }
}